// round 8
// baseline (speedup 1.0000x reference)
#include <cuda_runtime.h>

// Problem constants (fixed by the reference):
//   input : (32, 1, 1024, 1024) float32
//   x_A, y_A, x_B, y_B, ordinal : (32, 100000) i32
//   output: scalar float32 = mean loss over 3.2M points
//
// Converged design notes (R2-R7 evidence):
//  - pinned at ~207 MB DRAM vs ~192 MB compulsory floor (64B L2-miss granule)
//  - occupancy / L2 hints / offset-folding: non-binding or harmful
//  - __ldcg gathers (no L1 alloc): kept (-1.2 us)
//  - R8: PPT=16 -> 782 blocks = single wave (was 1.32 waves)
#define BB    32
#define HH    1024
#define WW    1024
#define NPTS  100000
#define TOTAL (BB * NPTS)        // 3,200,000
#define PPT   16                 // points per thread (NPTS % 16 == 0)
#define HALF  8
#define NTHREADS (TOTAL / PPT)   // 200,000
#define TPB   256
#define NBLOCKS ((NTHREADS + TPB - 1) / TPB)  // 782 (last block partial)

__device__ double       g_acc   = 0.0;
__device__ unsigned int g_count = 0;

// One 8-point slice: R6-proven structure (indices -> 16 gathers -> ordinals -> math)
__device__ __forceinline__ float slice8(
    const float* __restrict__ img,
    const int4* __restrict__ xA4, const int4* __restrict__ yA4,
    const int4* __restrict__ xB4, const int4* __restrict__ yB4,
    const int4* __restrict__ ov4, int g)
{
    int4 ax0 = __ldcs(xA4 + g);
    int4 ax1 = __ldcs(xA4 + g + 1);
    int4 ay0 = __ldcs(yA4 + g);
    int4 ay1 = __ldcs(yA4 + g + 1);
    int4 bx0 = __ldcs(xB4 + g);
    int4 bx1 = __ldcs(xB4 + g + 1);
    int4 by0 = __ldcs(yB4 + g);
    int4 by1 = __ldcs(yB4 + g + 1);

    int axv[HALF] = {ax0.x, ax0.y, ax0.z, ax0.w, ax1.x, ax1.y, ax1.z, ax1.w};
    int ayv[HALF] = {ay0.x, ay0.y, ay0.z, ay0.w, ay1.x, ay1.y, ay1.z, ay1.w};
    int bxv[HALF] = {bx0.x, bx0.y, bx0.z, bx0.w, bx1.x, bx1.y, bx1.z, bx1.w};
    int byv[HALF] = {by0.x, by0.y, by0.z, by0.w, by1.x, by1.y, by1.z, by1.w};

    // 16 random 4B gathers, L2-only, issued back-to-back
    float zA[HALF], zB[HALF];
    #pragma unroll
    for (int k = 0; k < HALF; k++) {
        zA[k] = __ldcg(&img[ayv[k] * WW + axv[k]]);
        zB[k] = __ldcg(&img[byv[k] * WW + bxv[k]]);
    }

    int4 ov0 = __ldcs(ov4 + g);
    int4 ov1 = __ldcs(ov4 + g + 1);
    int ovv[HALF] = {ov0.x, ov0.y, ov0.z, ov0.w, ov1.x, ov1.y, ov1.z, ov1.w};

    float l = 0.0f;
    #pragma unroll
    for (int k = 0; k < HALF; k++) {
        float diff = zA[k] - zB[k];
        float gt   = (float)(ovv[k] - 1);        // -1, 0, +1
        float mask = fabsf(gt);                  // 0 or 1
        float x    = -gt * diff;
        float sp   = fmaxf(x, 0.0f) + log1pf(expf(-fabsf(x)));
        l += mask * sp + (1.0f - mask) * diff * diff;
    }
    return l;
}

__global__ __launch_bounds__(TPB) void loss_kernel(
    const float* __restrict__ depth,
    const int*   __restrict__ xA,
    const int*   __restrict__ yA,
    const int*   __restrict__ xB,
    const int*   __restrict__ yB,
    const int*   __restrict__ ordv,
    float*       __restrict__ out)
{
    const int t = blockIdx.x * TPB + threadIdx.x;   // 0 .. 200191

    float l = 0.0f;
    if (t < NTHREADS) {
        // NPTS % 16 == 0 -> all 16 points of this thread share one batch
        const int b = t / (NPTS / PPT);             // t / 6250
        const float* __restrict__ img = depth + (size_t)b * (HH * WW);

        const int4* xA4 = (const int4*)xA;
        const int4* yA4 = (const int4*)yA;
        const int4* xB4 = (const int4*)xB;
        const int4* yB4 = (const int4*)yB;
        const int4* ov4 = (const int4*)ordv;

        const int g = 4 * t;   // first int4 group of this thread (4 groups total)
        l  = slice8(img, xA4, yA4, xB4, yB4, ov4, g);
        l += slice8(img, xA4, yA4, xB4, yB4, ov4, g + 2);
    }

    // Warp reduction
    #pragma unroll
    for (int off = 16; off > 0; off >>= 1)
        l += __shfl_down_sync(0xffffffffu, l, off);

    __shared__ float warpsums[TPB / 32];
    const int lane = threadIdx.x & 31;
    const int wid  = threadIdx.x >> 5;
    if (lane == 0) warpsums[wid] = l;
    __syncthreads();

    __shared__ bool isLast;
    if (wid == 0) {
        float s = (lane < (TPB / 32)) ? warpsums[lane] : 0.0f;
        #pragma unroll
        for (int off = 4; off > 0; off >>= 1)
            s += __shfl_down_sync(0xffffffffu, s, off);
        if (lane == 0) {
            atomicAdd(&g_acc, (double)s);
            __threadfence();
            unsigned int old = atomicAdd(&g_count, 1u);
            isLast = (old == (unsigned int)(gridDim.x - 1));
        }
    }
    __syncthreads();

    // Last block finalizes and resets state for the next graph replay
    if (isLast && threadIdx.x == 0) {
        __threadfence();
        double acc = *((volatile double*)&g_acc);
        *out = (float)(acc / (double)TOTAL);
        *((volatile double*)&g_acc) = 0.0;
        __threadfence();
        *((volatile unsigned int*)&g_count) = 0u;
    }
}

extern "C" void kernel_launch(void* const* d_in, const int* in_sizes, int n_in,
                              void* d_out, int out_size)
{
    const float* depth = (const float*)d_in[0];
    const int*   xA    = (const int*)d_in[1];
    const int*   yA    = (const int*)d_in[2];
    const int*   xB    = (const int*)d_in[3];
    const int*   yB    = (const int*)d_in[4];
    const int*   ordv  = (const int*)d_in[5];
    float*       out   = (float*)d_out;

    loss_kernel<<<NBLOCKS, TPB>>>(depth, xA, yA, xB, yB, ordv, out);
}

// round 9
// speedup vs baseline: 1.2972x; 1.2972x over previous
#include <cuda_runtime.h>

// Problem constants (fixed by the reference):
//   input : (32, 1, 1024, 1024) float32
//   x_A, y_A, x_B, y_B, ordinal : (32, 100000) int32
//   output: scalar float32 = mean loss over 3.2M points
//
// Design (R2-R8 evidence):
//  - memory wall: ~207 MB DRAM compulsory-ish; DRAM busy 60% at low pressure,
//    73% reachable under higher pressure -> raise pressure w/o extra traffic
//  - index loads MUST be warp-consecutive (R8: striding -> 2.2x traffic)
//  - __ldcg gathers (no L1 alloc) win; __ldcs streaming indices
//  - PPT=16 via TWO far-apart coalesced 8-point slices; 782 blocks ~ 1 wave
#define BB    32
#define HH    1024
#define WW    1024
#define NPTS  100000
#define TOTAL (BB * NPTS)        // 3,200,000
#define HALF  8
#define NTHREADS (TOTAL / 16)    // 200,000 threads, 16 points each
#define HALFPTS (TOTAL / 2)      // 1,600,000 point offset between slices
#define HALFGRP (HALFPTS / 4)    // 400,000 int4-group offset
#define TPB   256
#define NBLOCKS ((NTHREADS + TPB - 1) / TPB)  // 782 (last block partial)

__device__ double       g_acc   = 0.0;
__device__ unsigned int g_count = 0;

// One 8-point slice, R6-proven structure. g = first int4 group (warp-consecutive
// when g = 2t + const). img must be the depth image for batch (4g)/NPTS.
__device__ __forceinline__ float slice8(
    const float* __restrict__ img,
    const int4* __restrict__ xA4, const int4* __restrict__ yA4,
    const int4* __restrict__ xB4, const int4* __restrict__ yB4,
    const int4* __restrict__ ov4, int g)
{
    int4 ax0 = __ldcs(xA4 + g);
    int4 ax1 = __ldcs(xA4 + g + 1);
    int4 ay0 = __ldcs(yA4 + g);
    int4 ay1 = __ldcs(yA4 + g + 1);
    int4 bx0 = __ldcs(xB4 + g);
    int4 bx1 = __ldcs(xB4 + g + 1);
    int4 by0 = __ldcs(yB4 + g);
    int4 by1 = __ldcs(yB4 + g + 1);

    int axv[HALF] = {ax0.x, ax0.y, ax0.z, ax0.w, ax1.x, ax1.y, ax1.z, ax1.w};
    int ayv[HALF] = {ay0.x, ay0.y, ay0.z, ay0.w, ay1.x, ay1.y, ay1.z, ay1.w};
    int bxv[HALF] = {bx0.x, bx0.y, bx0.z, bx0.w, bx1.x, bx1.y, bx1.z, bx1.w};
    int byv[HALF] = {by0.x, by0.y, by0.z, by0.w, by1.x, by1.y, by1.z, by1.w};

    // 16 random 4B gathers, L2-only, issued back-to-back
    float zA[HALF], zB[HALF];
    #pragma unroll
    for (int k = 0; k < HALF; k++) {
        zA[k] = __ldcg(&img[ayv[k] * WW + axv[k]]);
        zB[k] = __ldcg(&img[byv[k] * WW + bxv[k]]);
    }

    int4 ov0 = __ldcs(ov4 + g);
    int4 ov1 = __ldcs(ov4 + g + 1);
    int ovv[HALF] = {ov0.x, ov0.y, ov0.z, ov0.w, ov1.x, ov1.y, ov1.z, ov1.w};

    float l = 0.0f;
    #pragma unroll
    for (int k = 0; k < HALF; k++) {
        float diff = zA[k] - zB[k];
        float gt   = (float)(ovv[k] - 1);        // -1, 0, +1
        float mask = fabsf(gt);                  // 0 or 1
        float x    = -gt * diff;
        float sp   = fmaxf(x, 0.0f) + log1pf(expf(-fabsf(x)));
        l += mask * sp + (1.0f - mask) * diff * diff;
    }
    return l;
}

__global__ __launch_bounds__(TPB) void loss_kernel(
    const float* __restrict__ depth,
    const int*   __restrict__ xA,
    const int*   __restrict__ yA,
    const int*   __restrict__ xB,
    const int*   __restrict__ yB,
    const int*   __restrict__ ordv,
    float*       __restrict__ out)
{
    const int t = blockIdx.x * TPB + threadIdx.x;   // 0 .. 200191

    float l = 0.0f;
    if (t < NTHREADS) {
        const int4* xA4 = (const int4*)xA;
        const int4* yA4 = (const int4*)yA;
        const int4* xB4 = (const int4*)xB;
        const int4* yB4 = (const int4*)yB;
        const int4* ov4 = (const int4*)ordv;

        // Slice 1: points [8t, 8t+8). NPTS % 8 == 0 -> single batch.
        const int b1 = t / (NPTS / 8);              // (8t)/NPTS
        const float* __restrict__ img1 = depth + (size_t)b1 * (HH * WW);
        l = slice8(img1, xA4, yA4, xB4, yB4, ov4, 2 * t);

        // Slice 2: same pattern, offset by half the dataset (batch b1 + 16).
        const float* __restrict__ img2 = img1 + (size_t)(BB / 2) * (HH * WW);
        l += slice8(img2, xA4, yA4, xB4, yB4, ov4, HALFGRP + 2 * t);
    }

    // Warp reduction
    #pragma unroll
    for (int off = 16; off > 0; off >>= 1)
        l += __shfl_down_sync(0xffffffffu, l, off);

    __shared__ float warpsums[TPB / 32];
    const int lane = threadIdx.x & 31;
    const int wid  = threadIdx.x >> 5;
    if (lane == 0) warpsums[wid] = l;
    __syncthreads();

    __shared__ bool isLast;
    if (wid == 0) {
        float s = (lane < (TPB / 32)) ? warpsums[lane] : 0.0f;
        #pragma unroll
        for (int off = 4; off > 0; off >>= 1)
            s += __shfl_down_sync(0xffffffffu, s, off);
        if (lane == 0) {
            atomicAdd(&g_acc, (double)s);
            __threadfence();
            unsigned int old = atomicAdd(&g_count, 1u);
            isLast = (old == (unsigned int)(gridDim.x - 1));
        }
    }
    __syncthreads();

    // Last block finalizes and resets state for the next graph replay
    if (isLast && threadIdx.x == 0) {
        __threadfence();
        double acc = *((volatile double*)&g_acc);
        *out = (float)(acc / (double)TOTAL);
        *((volatile double*)&g_acc) = 0.0;
        __threadfence();
        *((volatile unsigned int*)&g_count) = 0u;
    }
}

extern "C" void kernel_launch(void* const* d_in, const int* in_sizes, int n_in,
                              void* d_out, int out_size)
{
    const float* depth = (const float*)d_in[0];
    const int*   xA    = (const int*)d_in[1];
    const int*   yA    = (const int*)d_in[2];
    const int*   xB    = (const int*)d_in[3];
    const int*   yB    = (const int*)d_in[4];
    const int*   ordv  = (const int*)d_in[5];
    float*       out   = (float*)d_out;

    loss_kernel<<<NBLOCKS, TPB>>>(depth, xA, yA, xB, yB, ordv, out);
}

// round 10
// speedup vs baseline: 1.7528x; 1.3513x over previous
#include <cuda_runtime.h>

// Problem constants (fixed by the reference):
//   input : (32, 1, 1024, 1024) float32
//   x_A, y_A, x_B, y_B, ordinal : (32, 100000) int32
//   output: scalar float32 = mean loss over 3.2M points
//
// CONVERGED (R2-R9 evidence). This is the R6 configuration, the measured
// optimum:
//  - memory-wall bound: ~207 MB DRAM vs ~192 MB compulsory floor at 64B
//    L2-miss granularity; DRAM busy ~60% (random-access row overhead)
//  - occupancy (67% vs 88%), MLP (8 vs 16 vs 32 gathers/thread), wave count
//    (1.0 vs 1.3), L2 evict hints, offset-folding: all measured non-binding
//    or harmful (R5, R7, R8, R9)
//  - __ldcg gathers (L2-only, no L1 line allocation): -1.2 us, kept
//  - __ldcs streaming index loads, warp-consecutive int4 (R8 showed striding
//    costs 2.2x traffic)
//  - single launch: last-block finalize + state reset (graph-replay safe)
#define BB    32
#define HH    1024
#define WW    1024
#define NPTS  100000
#define TOTAL (BB * NPTS)        // 3,200,000
#define PPT   8                  // points per thread (NPTS % 8 == 0)
#define NTHREADS (TOTAL / PPT)   // 400,000
#define TPB   256
#define NBLOCKS ((NTHREADS + TPB - 1) / TPB)  // 1563 (last block partial)

__device__ double       g_acc   = 0.0;
__device__ unsigned int g_count = 0;

__global__ __launch_bounds__(TPB) void loss_kernel(
    const float* __restrict__ depth,
    const int*   __restrict__ xA,
    const int*   __restrict__ yA,
    const int*   __restrict__ xB,
    const int*   __restrict__ yB,
    const int*   __restrict__ ordv,
    float*       __restrict__ out)
{
    const int t = blockIdx.x * TPB + threadIdx.x;   // 0 .. 400127

    float l = 0.0f;
    if (t < NTHREADS) {
        // NPTS % 8 == 0 -> all 8 points of this thread share one batch
        const int b = t / (NPTS / PPT);             // t / 12500
        const float* __restrict__ img = depth + (size_t)b * (HH * WW);

        // Streaming vectorized index loads (touched once; evict-first in L2)
        const int4* xA4 = (const int4*)xA;
        const int4* yA4 = (const int4*)yA;
        const int4* xB4 = (const int4*)xB;
        const int4* yB4 = (const int4*)yB;
        const int4* ov4 = (const int4*)ordv;

        int4 ax0 = __ldcs(xA4 + 2 * t);
        int4 ax1 = __ldcs(xA4 + 2 * t + 1);
        int4 ay0 = __ldcs(yA4 + 2 * t);
        int4 ay1 = __ldcs(yA4 + 2 * t + 1);
        int4 bx0 = __ldcs(xB4 + 2 * t);
        int4 bx1 = __ldcs(xB4 + 2 * t + 1);
        int4 by0 = __ldcs(yB4 + 2 * t);
        int4 by1 = __ldcs(yB4 + 2 * t + 1);
        int4 ov0 = __ldcs(ov4 + 2 * t);
        int4 ov1 = __ldcs(ov4 + 2 * t + 1);

        int axv[PPT] = {ax0.x, ax0.y, ax0.z, ax0.w, ax1.x, ax1.y, ax1.z, ax1.w};
        int ayv[PPT] = {ay0.x, ay0.y, ay0.z, ay0.w, ay1.x, ay1.y, ay1.z, ay1.w};
        int bxv[PPT] = {bx0.x, bx0.y, bx0.z, bx0.w, bx1.x, bx1.y, bx1.z, bx1.w};
        int byv[PPT] = {by0.x, by0.y, by0.z, by0.w, by1.x, by1.y, by1.z, by1.w};
        int ovv[PPT] = {ov0.x, ov0.y, ov0.z, ov0.w, ov1.x, ov1.y, ov1.z, ov1.w};

        // Random 4B gathers: L2-only (.cg) — no L1 line allocation.
        // All 16 issued back-to-back for max MLP.
        float zA[PPT], zB[PPT];
        #pragma unroll
        for (int k = 0; k < PPT; k++) {
            zA[k] = __ldcg(&img[ayv[k] * WW + axv[k]]);
            zB[k] = __ldcg(&img[byv[k] * WW + bxv[k]]);
        }

        #pragma unroll
        for (int k = 0; k < PPT; k++) {
            float diff = zA[k] - zB[k];
            float gt   = (float)(ovv[k] - 1);        // -1, 0, +1
            float mask = fabsf(gt);                  // 0 or 1
            float x    = -gt * diff;
            float sp   = fmaxf(x, 0.0f) + log1pf(expf(-fabsf(x)));
            l += mask * sp + (1.0f - mask) * diff * diff;
        }
    }

    // Warp reduction
    #pragma unroll
    for (int off = 16; off > 0; off >>= 1)
        l += __shfl_down_sync(0xffffffffu, l, off);

    __shared__ float warpsums[TPB / 32];
    const int lane = threadIdx.x & 31;
    const int wid  = threadIdx.x >> 5;
    if (lane == 0) warpsums[wid] = l;
    __syncthreads();

    __shared__ bool isLast;
    if (wid == 0) {
        float s = (lane < (TPB / 32)) ? warpsums[lane] : 0.0f;
        #pragma unroll
        for (int off = 4; off > 0; off >>= 1)
            s += __shfl_down_sync(0xffffffffu, s, off);
        if (lane == 0) {
            atomicAdd(&g_acc, (double)s);
            __threadfence();
            unsigned int old = atomicAdd(&g_count, 1u);
            isLast = (old == (unsigned int)(gridDim.x - 1));
        }
    }
    __syncthreads();

    // Last block finalizes and resets state for the next graph replay
    if (isLast && threadIdx.x == 0) {
        __threadfence();
        double acc = *((volatile double*)&g_acc);
        *out = (float)(acc / (double)TOTAL);
        *((volatile double*)&g_acc) = 0.0;
        __threadfence();
        *((volatile unsigned int*)&g_count) = 0u;
    }
}

extern "C" void kernel_launch(void* const* d_in, const int* in_sizes, int n_in,
                              void* d_out, int out_size)
{
    const float* depth = (const float*)d_in[0];
    const int*   xA    = (const int*)d_in[1];
    const int*   yA    = (const int*)d_in[2];
    const int*   xB    = (const int*)d_in[3];
    const int*   yB    = (const int*)d_in[4];
    const int*   ordv  = (const int*)d_in[5];
    float*       out   = (float*)d_out;

    loss_kernel<<<NBLOCKS, TPB>>>(depth, xA, yA, xB, yB, ordv, out);
}